// round 1
// baseline (speedup 1.0000x reference)
#include <cuda_runtime.h>
#include <math.h>

#define N_IN   128
#define NLAY   6
#define N_H    320
#define DEG    32
#define N_OUT  18
#define BATCH  8192
#define BT     32            // batch rows per CTA (== warp lanes)
#define SMEM_NODES 1728      // N_IN + 5*N_H : nodes kept in shared
#define NTILES (BATCH / BT)  // 256 CTAs
#define NWARPS 16
#define NTHREADS (NWARPS * 32)

// Per-tile scratch for layer-5 activations (nodes [1728,2048)), read only by
// the output head. Static __device__ array: no allocation, graph-safe.
__device__ float g_scratch[(size_t)NTILES * N_H * BT];

__global__ void __launch_bounds__(NTHREADS, 1)
policy_kernel(const float* __restrict__ obs,      // [BATCH, N_IN]
              const int*   __restrict__ hid_src,  // [NLAY, N_H, DEG]
              const float* __restrict__ hid_w,    // [NLAY, N_H, DEG]
              const float* __restrict__ hid_b,    // [NLAY, N_H]
              const int*   __restrict__ out_src,  // [N_OUT, DEG]
              const float* __restrict__ out_w,    // [N_OUT, DEG]
              const float* __restrict__ out_b,    // [N_OUT]
              float*       __restrict__ out)      // [BATCH, N_OUT]
{
    extern __shared__ float sacts[];   // [SMEM_NODES][BT], node-major
    const int lane = threadIdx.x & 31;
    const int warp = threadIdx.x >> 5;
    const int tile = blockIdx.x;
    const int b    = tile * BT + lane;

    float* __restrict__ sa = sacts + lane;   // gather base: addr = idx*BT (+lane)

    // ---- Load obs transposed into node-major smem.
    // Strided LDG (stride 512B) — small one-time cost, L2-resident after wave 1.
    #pragma unroll
    for (int i = warp; i < N_IN; i += NWARPS)
        sacts[i * BT + lane] = obs[(size_t)b * N_IN + i];
    __syncthreads();

    float* __restrict__ scr = g_scratch + (size_t)tile * (N_H * BT);

    // ---- Hidden layers: warp = one neuron x 32 batch lanes.
    for (int l = 0; l < NLAY; l++) {
        const int4*   srcl = (const int4*)  (hid_src + (size_t)l * N_H * DEG);
        const float4* wl   = (const float4*)(hid_w   + (size_t)l * N_H * DEG);
        const float*  bl   = hid_b + l * N_H;
        const int wbase = N_IN + l * N_H;
        const bool last = (l == NLAY - 1);

        for (int n = warp; n < N_H; n += NWARPS) {
            const int4*   sp = srcl + n * (DEG / 4);
            const float4* wp = wl   + n * (DEG / 4);
            float a0 = 0.f, a1 = 0.f, a2 = 0.f, a3 = 0.f;
            #pragma unroll
            for (int c = 0; c < DEG / 4; c++) {
                const int4   i4 = sp[c];     // uniform LDG.128 (L2-hot)
                const float4 w4 = wp[c];     // uniform LDG.128 (L2-hot)
                a0 += sa[i4.x * BT] * w4.x;  // LDS.32, conflict-free (bank = lane)
                a1 += sa[i4.y * BT] * w4.y;
                a2 += sa[i4.z * BT] * w4.z;
                a3 += sa[i4.w * BT] * w4.w;
            }
            const float h = tanhf((a0 + a1) + (a2 + a3) + bl[n]);
            if (!last)
                sacts[(wbase + n) * BT + lane] = h;   // conflict-free STS
            else
                scr[n * BT + lane] = h;               // coalesced 128B STG
        }
        __syncthreads();  // also orders the layer-5 global stores for the head
    }

    // ---- Output head: 18 neurons. Sources may hit layer-5 (scratch) region.
    for (int o = warp; o < N_OUT; o += NWARPS) {
        const int4*   sp = (const int4*)  (out_src + o * DEG);
        const float4* wp = (const float4*)(out_w   + o * DEG);
        float a0 = 0.f, a1 = 0.f, a2 = 0.f, a3 = 0.f;
        #pragma unroll
        for (int c = 0; c < DEG / 4; c++) {
            const int4   i4 = sp[c];
            const float4 w4 = wp[c];
            // idx is warp-uniform -> no divergence
            const float vx = (i4.x < SMEM_NODES) ? sa[i4.x * BT] : scr[(i4.x - SMEM_NODES) * BT + lane];
            const float vy = (i4.y < SMEM_NODES) ? sa[i4.y * BT] : scr[(i4.y - SMEM_NODES) * BT + lane];
            const float vz = (i4.z < SMEM_NODES) ? sa[i4.z * BT] : scr[(i4.z - SMEM_NODES) * BT + lane];
            const float vw = (i4.w < SMEM_NODES) ? sa[i4.w * BT] : scr[(i4.w - SMEM_NODES) * BT + lane];
            a0 += vx * w4.x;
            a1 += vy * w4.y;
            a2 += vz * w4.z;
            a3 += vw * w4.w;
        }
        out[(size_t)b * N_OUT + o] = tanhf((a0 + a1) + (a2 + a3) + out_b[o]);
    }
}

extern "C" void kernel_launch(void* const* d_in, const int* in_sizes, int n_in,
                              void* d_out, int out_size)
{
    const float* obs     = (const float*)d_in[0];
    const int*   hid_src = (const int*)  d_in[1];
    const float* hid_w   = (const float*)d_in[2];
    const float* hid_b   = (const float*)d_in[3];
    const int*   out_src = (const int*)  d_in[4];
    const float* out_w   = (const float*)d_in[5];
    const float* out_b   = (const float*)d_in[6];
    float*       out     = (float*)d_out;

    const size_t smem = (size_t)SMEM_NODES * BT * sizeof(float);  // 221,184 B
    cudaFuncSetAttribute(policy_kernel,
                         cudaFuncAttributeMaxDynamicSharedMemorySize, (int)smem);
    policy_kernel<<<NTILES, NTHREADS, smem>>>(obs, hid_src, hid_w, hid_b,
                                              out_src, out_w, out_b, out);
}

// round 2
// speedup vs baseline: 1.7933x; 1.7933x over previous
#include <cuda_runtime.h>
#include <cuda_fp16.h>
#include <math.h>

#define N_IN   128
#define NLAY   6
#define N_H    320
#define DEG    32
#define N_OUT  18
#define BATCH  8192
#define BT     64            // batch rows per CTA (2 rows per lane, half2)
#define PAIRS  32            // row-pairs per tile == lanes
#define SMEM_NODES 1728      // N_IN + 5*N_H kept in shared
#define NTILES (BATCH / BT)  // 128 CTAs -> single wave on 148 SMs
#define NWARPS 16
#define NTHREADS (NWARPS * 32)
#define GSZ    16            // neurons per staged group (== NWARPS)
#define NGRP   (N_H / GSZ)   // 20 groups per layer
#define GMAX   18            // stage sized for the 18-neuron head group
#define SWORDS (GMAX * DEG)  // 576 words per stage array

// Layer-5 activations (nodes [1728,2048)) spill to global; head re-gathers them.
__device__ __half2 g_scratch[(size_t)NTILES * N_H * PAIRS];

struct SMem {
    __half2 acts[SMEM_NODES * PAIRS];  // 221,184 B  node-major, pair index = lane
    int     sidx[2][SWORDS];           //   4,608 B  double-buffered idx stage
    float   sw  [2][SWORDS];           //   4,608 B  double-buffered weight stage
};                                      // 230,400 B total

__global__ void __launch_bounds__(NTHREADS, 1)
policy_kernel(const float* __restrict__ obs,      // [BATCH, N_IN]
              const int*   __restrict__ hid_src,  // [NLAY, N_H, DEG]
              const float* __restrict__ hid_w,    // [NLAY, N_H, DEG]
              const float* __restrict__ hid_b,    // [NLAY, N_H]
              const int*   __restrict__ out_src,  // [N_OUT, DEG]
              const float* __restrict__ out_w,    // [N_OUT, DEG]
              const float* __restrict__ out_b,    // [N_OUT]
              float*       __restrict__ out)      // [BATCH, N_OUT]
{
    extern __shared__ char raw[];
    SMem* s = (SMem*)raw;
    const int tid  = threadIdx.x;
    const int lane = tid & 31;
    const int warp = tid >> 5;
    const int tile = blockIdx.x;

    // ---- obs -> node-major half2 smem. Lane p owns batch rows (2p, 2p+1).
    {
        const int r0 = tile * BT + 2 * lane;
        const float4* o0 = (const float4*)(obs + (size_t)r0 * N_IN);
        const float4* o1 = (const float4*)(obs + (size_t)(r0 + 1) * N_IN);
        #pragma unroll
        for (int q = warp; q < N_IN / 4; q += NWARPS) {
            float4 a = o0[q], b = o1[q];
            s->acts[(q * 4 + 0) * PAIRS + lane] = __floats2half2_rn(a.x, b.x);
            s->acts[(q * 4 + 1) * PAIRS + lane] = __floats2half2_rn(a.y, b.y);
            s->acts[(q * 4 + 2) * PAIRS + lane] = __floats2half2_rn(a.z, b.z);
            s->acts[(q * 4 + 3) * PAIRS + lane] = __floats2half2_rn(a.w, b.w);
        }
    }

    // Coalesced prefetch of one 16-neuron group (512 words each = exactly 1/thread).
    auto pre_hidden = [&](int l, int g, int bufi) {
        const int base = (l * N_H + g * GSZ) * DEG;
        s->sidx[bufi][tid] = hid_src[base + tid];
        s->sw  [bufi][tid] = hid_w  [base + tid];
    };

    pre_hidden(0, 0, 0);

    __half2* __restrict__ sa  = s->acts + lane;
    __half2* __restrict__ scr = g_scratch + (size_t)tile * (N_H * PAIRS) + lane;

    int buf = 0;
    for (int l = 0; l < NLAY; l++) {
        const float* bl = hid_b + l * N_H;
        for (int g = 0; g < NGRP; g++) {
            __syncthreads();  // stage[buf] ready; prev group's acts visible

            // ---- prefetch next group into buf^1 (overlaps compute below)
            if (g + 1 < NGRP)      pre_hidden(l, g + 1, buf ^ 1);
            else if (l + 1 < NLAY) pre_hidden(l + 1, 0, buf ^ 1);
            else {                 // head stage: 576 words
                s->sidx[buf ^ 1][tid] = out_src[tid];
                s->sw  [buf ^ 1][tid] = out_w  [tid];
                if (tid < SWORDS - NTHREADS) {
                    s->sidx[buf ^ 1][tid + NTHREADS] = out_src[tid + NTHREADS];
                    s->sw  [buf ^ 1][tid + NTHREADS] = out_w  [tid + NTHREADS];
                }
            }

            // ---- compute: warp = one neuron x 64 batch rows
            const int n = g * GSZ + warp;
            const int4*   ip = (const int4*)  (s->sidx[buf] + warp * DEG);  // LDS.128 bcast
            const float4* wp = (const float4*)(s->sw  [buf] + warp * DEG);
            float al0 = 0.f, ah0 = 0.f, al1 = 0.f, ah1 = 0.f;
            #pragma unroll
            for (int c = 0; c < DEG / 4; c++) {
                const int4   i4 = ip[c];
                const float4 w4 = wp[c];
                float2 f;
                f = __half22float2(sa[i4.x * PAIRS]); al0 += f.x * w4.x; ah0 += f.y * w4.x;
                f = __half22float2(sa[i4.y * PAIRS]); al1 += f.x * w4.y; ah1 += f.y * w4.y;
                f = __half22float2(sa[i4.z * PAIRS]); al0 += f.x * w4.z; ah0 += f.y * w4.z;
                f = __half22float2(sa[i4.w * PAIRS]); al1 += f.x * w4.w; ah1 += f.y * w4.w;
            }
            const float bb = bl[n];
            const float hl = tanhf(al0 + al1 + bb);
            const float hh = tanhf(ah0 + ah1 + bb);
            const __half2 hv = __floats2half2_rn(hl, hh);
            if (l < NLAY - 1) sa [(N_IN + l * N_H + n) * PAIRS] = hv;  // conflict-free STS
            else              scr[n * PAIRS] = hv;                     // coalesced STG
            buf ^= 1;
        }
    }

    __syncthreads();  // layer-5 scratch + head stage visible

    // ---- output head: 18 neurons, sources may hit layer-5 scratch
    {
        const int r0 = tile * BT + 2 * lane;
        for (int o = warp; o < N_OUT; o += NWARPS) {
            const int4*   ip = (const int4*)  (s->sidx[buf] + o * DEG);
            const float4* wp = (const float4*)(s->sw  [buf] + o * DEG);
            float al = 0.f, ah = 0.f;
            #pragma unroll
            for (int c = 0; c < DEG / 4; c++) {
                const int4   i4 = ip[c];
                const float4 w4 = wp[c];
                #define GATH(IDX, W) { const int ii = (IDX);                              \
                    const __half2 v = (ii < SMEM_NODES) ? sa[ii * PAIRS]                  \
                                                        : scr[(ii - SMEM_NODES) * PAIRS]; \
                    const float2 f = __half22float2(v); al += f.x * (W); ah += f.y * (W); }
                GATH(i4.x, w4.x); GATH(i4.y, w4.y); GATH(i4.z, w4.z); GATH(i4.w, w4.w);
                #undef GATH
            }
            const float bo = out_b[o];
            out[(size_t)r0       * N_OUT + o] = tanhf(al + bo);
            out[(size_t)(r0 + 1) * N_OUT + o] = tanhf(ah + bo);
        }
    }
}

extern "C" void kernel_launch(void* const* d_in, const int* in_sizes, int n_in,
                              void* d_out, int out_size)
{
    const float* obs     = (const float*)d_in[0];
    const int*   hid_src = (const int*)  d_in[1];
    const float* hid_w   = (const float*)d_in[2];
    const float* hid_b   = (const float*)d_in[3];
    const int*   out_src = (const int*)  d_in[4];
    const float* out_w   = (const float*)d_in[5];
    const float* out_b   = (const float*)d_in[6];
    float*       out     = (float*)d_out;

    const size_t smem = sizeof(SMem);  // 230,400 B
    cudaFuncSetAttribute(policy_kernel,
                         cudaFuncAttributeMaxDynamicSharedMemorySize, (int)smem);
    policy_kernel<<<NTILES, NTHREADS, smem>>>(obs, hid_src, hid_w, hid_b,
                                              out_src, out_w, out_b, out);
}

// round 3
// speedup vs baseline: 2.2744x; 1.2683x over previous
#include <cuda_runtime.h>
#include <cuda_fp16.h>
#include <math.h>

#define N_IN   128
#define NLAY   6
#define N_H    320
#define DEG    32
#define N_OUT  18
#define BATCH  8192
#define BT     64            // batch rows per CTA (2 per lane via half2)
#define PAIRS  32            // row-pairs per tile == lanes
#define SMEM_NODES 1728      // N_IN + 5*N_H kept in shared
#define NTILES (BATCH / BT)  // 128 CTAs
#define NWARPS 32
#define NTHREADS (NWARPS * 32)   // 1024
#define GSZ    32            // neurons per staged group (== NWARPS)
#define NGRP   (N_H / GSZ)   // 10 groups per layer
#define SWORDS (GSZ * DEG)   // 1024 words per stage array (1 per thread)
#define HWORDS (N_OUT * DEG) // 576 words for the head stage

// Layer-5 activations (nodes [1728,2048)); head re-gathers them from global.
__device__ __half2 g_scratch[(size_t)NTILES * N_H * PAIRS];

struct SMem {
    __half2 acts[SMEM_NODES * PAIRS];  // 221,184 B node-major, pair = lane
    int     sidx[SWORDS];              //   4,096 B single-buffered idx stage
    float   sw  [SWORDS];              //   4,096 B single-buffered weight stage
};                                      // 229,376 B total

__global__ void __launch_bounds__(NTHREADS, 1)
policy_kernel(const float* __restrict__ obs,      // [BATCH, N_IN]
              const int*   __restrict__ hid_src,  // [NLAY, N_H, DEG]
              const float* __restrict__ hid_w,    // [NLAY, N_H, DEG]
              const float* __restrict__ hid_b,    // [NLAY, N_H]
              const int*   __restrict__ out_src,  // [N_OUT, DEG]
              const float* __restrict__ out_w,    // [N_OUT, DEG]
              const float* __restrict__ out_b,    // [N_OUT]
              float*       __restrict__ out)      // [BATCH, N_OUT]
{
    extern __shared__ char raw[];
    SMem* s = (SMem*)raw;
    const int tid  = threadIdx.x;
    const int lane = tid & 31;
    const int warp = tid >> 5;
    const int tile = blockIdx.x;

    // ---- obs -> node-major half2 smem. Lane p owns batch rows (2p, 2p+1).
    {
        const int r0 = tile * BT + 2 * lane;
        const float4* o0 = (const float4*)(obs + (size_t)r0 * N_IN);
        const float4* o1 = (const float4*)(obs + (size_t)(r0 + 1) * N_IN);
        const int q = warp;                  // 32 warps cover N_IN/4 = 32 quads
        float4 a = o0[q], b = o1[q];
        s->acts[(q * 4 + 0) * PAIRS + lane] = __floats2half2_rn(a.x, b.x);
        s->acts[(q * 4 + 1) * PAIRS + lane] = __floats2half2_rn(a.y, b.y);
        s->acts[(q * 4 + 2) * PAIRS + lane] = __floats2half2_rn(a.z, b.z);
        s->acts[(q * 4 + 3) * PAIRS + lane] = __floats2half2_rn(a.w, b.w);
    }

    __half2* __restrict__ sa  = s->acts + lane;
    __half2* __restrict__ scr = g_scratch + (size_t)tile * (N_H * PAIRS) + lane;

    // ---- Preload group (l=0, g=0) into the stage.
    {
        s->sidx[tid] = hid_src[tid];
        s->sw  [tid] = hid_w  [tid];
    }
    __syncthreads();

    int pidx = 0; float pw = 0.f;   // register double-buffer (1 word/thread)
    for (int l = 0; l < NLAY; l++) {
        const float* bl = hid_b + l * N_H;
        for (int g = 0; g < NGRP; g++) {
            // ---- prefetch next group's words into registers (overlaps compute)
            const bool lastg = (g == NGRP - 1);
            if (!lastg || l + 1 < NLAY) {
                const int nb = (l * N_H + (lastg ? (l + 1) * N_H - l * N_H /*next layer g0*/ : (g + 1) * GSZ) * 1) * DEG;
                // simpler: flat word offset of next group
                const int flat = (l * N_H + (lastg ? 0 : (g + 1) * GSZ)) * DEG
                               + (lastg ? (N_H) * DEG * 0 : 0);
                const int base = lastg ? ((l + 1) * N_H) * DEG : (l * N_H + (g + 1) * GSZ) * DEG;
                (void)nb; (void)flat;
                pidx = hid_src[base + tid];
                pw   = hid_w  [base + tid];
            } else if (tid < HWORDS) {       // head stage
                pidx = out_src[tid];
                pw   = out_w  [tid];
            }

            // ---- compute: warp = one neuron x 64 batch rows
            const int n = g * GSZ + warp;
            const int4*   ip = (const int4*)  (s->sidx + warp * DEG);  // LDS.128 bcast
            const float4* wp = (const float4*)(s->sw   + warp * DEG);
            float al0 = 0.f, ah0 = 0.f, al1 = 0.f, ah1 = 0.f;
            #pragma unroll
            for (int c = 0; c < DEG / 4; c++) {
                const int4   i4 = ip[c];
                const float4 w4 = wp[c];
                float2 f;
                f = __half22float2(sa[i4.x * PAIRS]); al0 += f.x * w4.x; ah0 += f.y * w4.x;
                f = __half22float2(sa[i4.y * PAIRS]); al1 += f.x * w4.y; ah1 += f.y * w4.y;
                f = __half22float2(sa[i4.z * PAIRS]); al0 += f.x * w4.z; ah0 += f.y * w4.z;
                f = __half22float2(sa[i4.w * PAIRS]); al1 += f.x * w4.w; ah1 += f.y * w4.w;
            }
            const float bb = bl[n];
            const float hl = tanhf(al0 + al1 + bb);
            const float hh = tanhf(ah0 + ah1 + bb);
            const __half2 hv = __floats2half2_rn(hl, hh);
            if (l < NLAY - 1) sa [(N_IN + l * N_H + n) * PAIRS] = hv;  // STS
            else              scr[n * PAIRS] = hv;                     // STG

            __syncthreads();                 // all reads of stage done
            if (l + 1 < NLAY || !lastg || tid < HWORDS) {
                s->sidx[tid] = pidx;         // publish next group's stage
                s->sw  [tid] = pw;
            }
            __syncthreads();                 // stage (and prev acts) ready
        }
    }

    // ---- output head: 18 neurons (warps 0..17); sources may hit scratch.
    if (warp < N_OUT) {
        const int o = warp;
        const int4*   ip = (const int4*)  (s->sidx + o * DEG);
        const float4* wp = (const float4*)(s->sw   + o * DEG);
        float al = 0.f, ah = 0.f;
        #pragma unroll
        for (int c = 0; c < DEG / 4; c++) {
            const int4   i4 = ip[c];
            const float4 w4 = wp[c];
            #define GATH(IDX, W) { const int ii = (IDX);                              \
                const __half2 v = (ii < SMEM_NODES) ? sa[ii * PAIRS]                  \
                                                    : scr[(ii - SMEM_NODES) * PAIRS]; \
                const float2 f = __half22float2(v); al += f.x * (W); ah += f.y * (W); }
            GATH(i4.x, w4.x); GATH(i4.y, w4.y); GATH(i4.z, w4.z); GATH(i4.w, w4.w);
            #undef GATH
        }
        const float bo = out_b[o];
        const int r0 = tile * BT + 2 * lane;
        out[(size_t)r0       * N_OUT + o] = tanhf(al + bo);
        out[(size_t)(r0 + 1) * N_OUT + o] = tanhf(ah + bo);
    }
}

extern "C" void kernel_launch(void* const* d_in, const int* in_sizes, int n_in,
                              void* d_out, int out_size)
{
    const float* obs     = (const float*)d_in[0];
    const int*   hid_src = (const int*)  d_in[1];
    const float* hid_w   = (const float*)d_in[2];
    const float* hid_b   = (const float*)d_in[3];
    const int*   out_src = (const int*)  d_in[4];
    const float* out_w   = (const float*)d_in[5];
    const float* out_b   = (const float*)d_in[6];
    float*       out     = (float*)d_out;

    const size_t smem = sizeof(SMem);  // 229,376 B
    cudaFuncSetAttribute(policy_kernel,
                         cudaFuncAttributeMaxDynamicSharedMemorySize, (int)smem);
    policy_kernel<<<NTILES, NTHREADS, smem>>>(obs, hid_src, hid_w, hid_b,
                                              out_src, out_w, out_b, out);
}